// round 6
// baseline (speedup 1.0000x reference)
#include <cuda_runtime.h>
#include <cuda_bf16.h>
#include <math.h>
#include <stdint.h>
#include <stddef.h>

// Problem shape: N = M = 8192, QDIM = KDIM = 1024, MID = 512
// ---------------------------------------------------------------------------
// Device scratch (no allocation allowed anywhere)
// ---------------------------------------------------------------------------
static __device__ __nv_bfloat16 g_Qh[(size_t)8192 * 512];
static __device__ __nv_bfloat16 g_Ql[(size_t)8192 * 512];
static __device__ __nv_bfloat16 g_Kh[(size_t)8192 * 512];
static __device__ __nv_bfloat16 g_Kl[(size_t)8192 * 512];
static __device__ __nv_bfloat16 g_VhT[(size_t)1024 * 8192];  // [n][k]
static __device__ __nv_bfloat16 g_VlT[(size_t)1024 * 8192];
static __device__ __nv_bfloat16 g_Ph[(size_t)8192 * 8192];   // 128 MB
static __device__ __nv_bfloat16 g_Pl[(size_t)8192 * 8192];   // 128 MB
static __device__ float g_partial[(size_t)64 * 8192];
static __device__ float g_denom[8192];
static __device__ unsigned char g_M[(size_t)8192 * 8192];
static __device__ int g_mask_w1;

// ---------------------------------------------------------------------------
// PTX helpers: all plain sm_80-era ISA (valid on .target sm_100)
// ---------------------------------------------------------------------------
__device__ __forceinline__ uint32_t smem_u32(const void* p) {
    uint32_t a;
    asm("{ .reg .u64 t; cvta.to.shared.u64 t, %1; cvt.u32.u64 %0, t; }"
        : "=r"(a) : "l"(p));
    return a;
}
#define LDSM4(r, addr) \
    asm volatile("ldmatrix.sync.aligned.m8n8.x4.shared.b16 {%0,%1,%2,%3}, [%4];" \
                 : "=r"((r)[0]), "=r"((r)[1]), "=r"((r)[2]), "=r"((r)[3]) \
                 : "r"(addr))
#define MMA16816(d, a, b) \
    asm volatile("mma.sync.aligned.m16n8k16.row.col.f32.bf16.bf16.f32 " \
                 "{%0,%1,%2,%3}, {%4,%5,%6,%7}, {%8,%9}, {%0,%1,%2,%3};" \
                 : "+f"((d)[0]), "+f"((d)[1]), "+f"((d)[2]), "+f"((d)[3]) \
                 : "r"((a)[0]), "r"((a)[1]), "r"((a)[2]), "r"((a)[3]), \
                   "r"((b)[0]), "r"((b)[1]))
#define CP16(saddr, gptr) \
    asm volatile("cp.async.cg.shared.global [%0], [%1], 16;" \
                 :: "r"(saddr), "l"(gptr))
#define CP_COMMIT() asm volatile("cp.async.commit_group;" ::: "memory")
#define CP_WAIT0()  asm volatile("cp.async.wait_group 0;" ::: "memory")

__device__ __forceinline__ unsigned int pack2(__nv_bfloat16 a, __nv_bfloat16 b) {
    const unsigned short ua = *(const unsigned short*)&a;
    const unsigned short ub = *(const unsigned short*)&b;
    return (unsigned int)ua | ((unsigned int)ub << 16);
}

// smem tile geometry: 128 rows x 32 bf16, padded row stride 40 bf16 = 80 B
#define ROWB 80
#define TILE_B (128 * ROWB)            // 10240 B
#define OFF_AH 0
#define OFF_AL (1 * TILE_B)
#define OFF_BH (2 * TILE_B)
#define OFF_BL (3 * TILE_B)
#define STAGE_B (4 * TILE_B)           // 40960 B
#define DYN_SMEM (2 * STAGE_B)         // 81920 B

// Fill one stage (4 tiles) via cp.async: 8 x 16B per thread.
__device__ __forceinline__ void fill_stage(
    uint32_t sbase,
    const __nv_bfloat16* __restrict__ Ah, const __nv_bfloat16* __restrict__ Al,
    size_t strideA, int rA,
    const __nv_bfloat16* __restrict__ Bh, const __nv_bfloat16* __restrict__ Bl,
    size_t strideB, int rB,
    int k0, int tid)
{
#pragma unroll
    for (int it = 0; it < 2; it++) {
        const int idx = it * 256 + tid;     // 0..511
        const int row = idx >> 2, seg = idx & 3;
        const uint32_t so = (uint32_t)(row * ROWB + seg * 16);
        const size_t ca = (size_t)(rA + row) * strideA + k0 + seg * 8;
        const size_t cb = (size_t)(rB + row) * strideB + k0 + seg * 8;
        CP16(sbase + OFF_AH + so, Ah + ca);
        CP16(sbase + OFF_AL + so, Al + ca);
        CP16(sbase + OFF_BH + so, Bh + cb);
        CP16(sbase + OFF_BL + so, Bl + cb);
    }
}

// Compute one BK=32 chunk: 2 k-steps, per warp 4x4 atoms x 3 products.
__device__ __forceinline__ void compute_chunk(
    uint32_t sbase, int wm, int wn, int lane, float acc[4][4][4])
{
    const int a_r = lane & 15, a_c = (lane >> 4) * 8;
    const int b_r = ((lane >> 4) & 1) * 8 + (lane & 7);
    const int b_c = ((lane >> 3) & 1) * 8;
#pragma unroll
    for (int ks = 0; ks < 2; ks++) {
        const int k0 = ks * 16;
        uint32_t ah[4][4], al[4][4];
#pragma unroll
        for (int ma = 0; ma < 4; ma++) {
            const uint32_t ra = sbase + OFF_AH +
                (uint32_t)((wm * 64 + ma * 16 + a_r) * ROWB + (k0 + a_c) * 2);
            LDSM4(ah[ma], ra);
            LDSM4(al[ma], ra + (OFF_AL - OFF_AH));
        }
        uint32_t bh[4][2], bl[4][2];
#pragma unroll
        for (int nb = 0; nb < 2; nb++) {
            const uint32_t rb = sbase + OFF_BH +
                (uint32_t)((wn * 32 + nb * 16 + b_r) * ROWB + (k0 + b_c) * 2);
            uint32_t t[4];
            LDSM4(t, rb);
            bh[nb * 2][0] = t[0]; bh[nb * 2][1] = t[1];
            bh[nb * 2 + 1][0] = t[2]; bh[nb * 2 + 1][1] = t[3];
            LDSM4(t, rb + (OFF_BL - OFF_BH));
            bl[nb * 2][0] = t[0]; bl[nb * 2][1] = t[1];
            bl[nb * 2 + 1][0] = t[2]; bl[nb * 2 + 1][1] = t[3];
        }
#pragma unroll
        for (int ma = 0; ma < 4; ma++)
#pragma unroll
            for (int na = 0; na < 4; na++) {
                MMA16816(acc[ma][na], ah[ma], bh[na]);
                MMA16816(acc[ma][na], ah[ma], bl[na]);
                MMA16816(acc[ma][na], al[ma], bh[na]);
            }
    }
}

// ---------------------------------------------------------------------------
// Mask dtype detection + normalization (proven in R3)
// ---------------------------------------------------------------------------
__global__ void detect_mask_kernel(const unsigned int* __restrict__ mw) {
    __shared__ int s_gt1, s_f32;
    if (threadIdx.x == 0) { s_gt1 = 0; s_f32 = 0; }
    __syncthreads();
    int gt1 = 0, f32 = 0;
    for (int i = threadIdx.x; i < 65536; i += blockDim.x) {
        const unsigned int w = mw[i];
        if (w == 0x3F800000u) f32 = 1;
        else if (w > 1u) gt1 = 1;
    }
    if (gt1) atomicOr(&s_gt1, 1);
    if (f32) atomicOr(&s_f32, 1);
    __syncthreads();
    if (threadIdx.x == 0) g_mask_w1 = (s_gt1 && !s_f32) ? 1 : 0;
}

__global__ void convert_mask_kernel(const void* __restrict__ mask_raw) {
    const int g = blockIdx.x * blockDim.x + threadIdx.x;
    unsigned int outw;
    if (g_mask_w1) {
        const unsigned int w = ((const unsigned int*)mask_raw)[g];
        outw = ((w & 0x000000FFu) ? 0x00000001u : 0u)
             | ((w & 0x0000FF00u) ? 0x00000100u : 0u)
             | ((w & 0x00FF0000u) ? 0x00010000u : 0u)
             | ((w & 0xFF000000u) ? 0x01000000u : 0u);
    } else {
        const uint4 v = ((const uint4*)mask_raw)[g];
        outw = (v.x ? 0x00000001u : 0u) | (v.y ? 0x00000100u : 0u)
             | (v.z ? 0x00010000u : 0u) | (v.w ? 0x01000000u : 0u);
    }
    ((unsigned int*)g_M)[g] = outw;
}

// ---------------------------------------------------------------------------
// Projection (fp32 SIMT, proven) with split-bf16 epilogue.
// ---------------------------------------------------------------------------
template <int OUTSEL>
__global__ void __launch_bounds__(256) proj_kernel(
    const float* __restrict__ A, const float* __restrict__ W,
    const float* __restrict__ bias)
{
    const int Kd = 1024, Ncols = 512;
    __nv_bfloat16* __restrict__ Ch = (OUTSEL == 0) ? g_Qh : g_Kh;
    __nv_bfloat16* __restrict__ Cl = (OUTSEL == 0) ? g_Ql : g_Kl;

    __shared__ __align__(16) float As[8][128];
    __shared__ __align__(16) float Bs[8][128];

    const int tid = threadIdx.x;
    const int tx = tid & 15, ty = tid >> 4;
    const int row0 = ty * 8, col0 = tx * 8;
    const int rBase = blockIdx.y * 128, cBase = blockIdx.x * 128;
    const int aRow = tid >> 1, aCol = (tid & 1) * 4;
    const int bRow = tid >> 5, bCol = (tid & 31) * 4;

    float acc[8][8] = {};

    for (int k0 = 0; k0 < Kd; k0 += 8) {
        float4 av = *(const float4*)(A + (size_t)(rBase + aRow) * Kd + k0 + aCol);
        As[aCol + 0][aRow] = av.x; As[aCol + 1][aRow] = av.y;
        As[aCol + 2][aRow] = av.z; As[aCol + 3][aRow] = av.w;
        *(float4*)(&Bs[bRow][bCol]) =
            *(const float4*)(W + (size_t)(k0 + bRow) * Ncols + cBase + bCol);
        __syncthreads();
#pragma unroll
        for (int k = 0; k < 8; k++) {
            float a[8], b[8];
#pragma unroll
            for (int i = 0; i < 8; i++) a[i] = As[k][row0 + i];
#pragma unroll
            for (int j = 0; j < 8; j++) b[j] = Bs[k][col0 + j];
#pragma unroll
            for (int i = 0; i < 8; i++)
#pragma unroll
                for (int j = 0; j < 8; j++)
                    acc[i][j] = fmaf(a[i], b[j], acc[i][j]);
        }
        __syncthreads();
    }

#pragma unroll
    for (int i = 0; i < 8; i++) {
        const size_t r = (size_t)(rBase + row0 + i);
#pragma unroll
        for (int j = 0; j < 8; j++) {
            const float x = acc[i][j] + bias[cBase + col0 + j];
            const __nv_bfloat16 h = __float2bfloat16(x);
            const __nv_bfloat16 l = __float2bfloat16(x - __bfloat162float(h));
            Ch[r * Ncols + cBase + col0 + j] = h;
            Cl[r * Ncols + cBase + col0 + j] = l;
        }
    }
}

// ---------------------------------------------------------------------------
// V^T split: g_VhT/g_VlT[n][k] = split(fix[k] * other[k][n])
// ---------------------------------------------------------------------------
__global__ void transpose_v_kernel(const float* __restrict__ other,
                                   const float* __restrict__ fix)
{
    __shared__ float t[32][33];
    const int kBase = blockIdx.x * 32, nBase = blockIdx.y * 32;
    const int tx = threadIdx.x, ty = threadIdx.y;
#pragma unroll
    for (int j = 0; j < 4; j++) {
        const int k = kBase + ty + j * 8;
        t[ty + j * 8][tx] = fix[k] * other[(size_t)k * 1024 + nBase + tx];
    }
    __syncthreads();
#pragma unroll
    for (int j = 0; j < 4; j++) {
        const int n = nBase + ty + j * 8;
        const float v = t[tx][ty + j * 8];
        const __nv_bfloat16 h = __float2bfloat16(v);
        const __nv_bfloat16 l = __float2bfloat16(v - __bfloat162float(h));
        g_VhT[(size_t)n * 8192 + kBase + tx] = h;
        g_VlT[(size_t)n * 8192 + kBase + tx] = l;
    }
}

// ---------------------------------------------------------------------------
// Pass A (mma.sync bf16x3): S = Q@K^T / sqrt(512); P = mask ? 0 : exp(S);
// split bf16 store + per-colblock row sums. grid = (64 col, 64 row), 256 thr.
// ---------------------------------------------------------------------------
__global__ void __launch_bounds__(256, 1) attn_exp_mma()
{
    extern __shared__ char dynsmem[];
    __shared__ float red[128][4];

    const int tid = threadIdx.x;
    const int lane = tid & 31, wid = tid >> 5;
    const int wm = wid >> 2, wn = wid & 3;
    const int rBase = blockIdx.y * 128, cBase = blockIdx.x * 128;
    const uint32_t sb = smem_u32(dynsmem);

    float acc[4][4][4] = {};

    const int NC = 16;  // 512 / 32
    fill_stage(sb, g_Qh, g_Ql, 512, rBase, g_Kh, g_Kl, 512, cBase, 0, tid);
    CP_COMMIT();
    for (int c = 0; c < NC; c++) {
        CP_WAIT0();
        __syncthreads();
        if (c + 1 < NC) {
            fill_stage(sb + ((c + 1) & 1) * STAGE_B,
                       g_Qh, g_Ql, 512, rBase, g_Kh, g_Kl, 512, cBase,
                       (c + 1) * 32, tid);
            CP_COMMIT();
        }
        compute_chunk(sb + (c & 1) * STAGE_B, wm, wn, lane, acc);
    }

    // epilogue: exp + mask + split store + rowsums
    const float scale = 0.044194173824159216f;  // 1/sqrt(512)
    const int g = lane >> 2, t4 = lane & 3;
    float rs_lo[4] = {}, rs_hi[4] = {};
#pragma unroll
    for (int ma = 0; ma < 4; ma++) {
        const int m_lo = rBase + wm * 64 + ma * 16 + g;
        const int m_hi = m_lo + 8;
#pragma unroll
        for (int na = 0; na < 4; na++) {
            const int n = cBase + wn * 32 + na * 8 + t4 * 2;
            {
                const unsigned short mk =
                    *(const unsigned short*)(g_M + (size_t)m_lo * 8192 + n);
                const float p0 = (mk & 0xFF) ? 0.0f : expf(acc[ma][na][0] * scale);
                const float p1 = (mk >> 8)   ? 0.0f : expf(acc[ma][na][1] * scale);
                const __nv_bfloat16 h0 = __float2bfloat16(p0);
                const __nv_bfloat16 l0 = __float2bfloat16(p0 - __bfloat162float(h0));
                const __nv_bfloat16 h1 = __float2bfloat16(p1);
                const __nv_bfloat16 l1 = __float2bfloat16(p1 - __bfloat162float(h1));
                *(unsigned int*)(g_Ph + (size_t)m_lo * 8192 + n) = pack2(h0, h1);
                *(unsigned int*)(g_Pl + (size_t)m_lo * 8192 + n) = pack2(l0, l1);
                rs_lo[ma] += __bfloat162float(h0) + __bfloat162float(l0)
                           + __bfloat162float(h1) + __bfloat162float(l1);
            }
            {
                const unsigned short mk =
                    *(const unsigned short*)(g_M + (size_t)m_hi * 8192 + n);
                const float p0 = (mk & 0xFF) ? 0.0f : expf(acc[ma][na][2] * scale);
                const float p1 = (mk >> 8)   ? 0.0f : expf(acc[ma][na][3] * scale);
                const __nv_bfloat16 h0 = __float2bfloat16(p0);
                const __nv_bfloat16 l0 = __float2bfloat16(p0 - __bfloat162float(h0));
                const __nv_bfloat16 h1 = __float2bfloat16(p1);
                const __nv_bfloat16 l1 = __float2bfloat16(p1 - __bfloat162float(h1));
                *(unsigned int*)(g_Ph + (size_t)m_hi * 8192 + n) = pack2(h0, h1);
                *(unsigned int*)(g_Pl + (size_t)m_hi * 8192 + n) = pack2(l0, l1);
                rs_hi[ma] += __bfloat162float(h0) + __bfloat162float(l0)
                           + __bfloat162float(h1) + __bfloat162float(l1);
            }
        }
    }
#pragma unroll
    for (int ma = 0; ma < 4; ma++) {
        float s = rs_lo[ma];
        s += __shfl_xor_sync(0xFFFFFFFFu, s, 1);
        s += __shfl_xor_sync(0xFFFFFFFFu, s, 2);
        float s2 = rs_hi[ma];
        s2 += __shfl_xor_sync(0xFFFFFFFFu, s2, 1);
        s2 += __shfl_xor_sync(0xFFFFFFFFu, s2, 2);
        if (t4 == 0) {
            red[wm * 64 + ma * 16 + g][wn] = s;
            red[wm * 64 + ma * 16 + g + 8][wn] = s2;
        }
    }
    __syncthreads();
    if (tid < 128) {
        const float s = red[tid][0] + red[tid][1] + red[tid][2] + red[tid][3];
        g_partial[(size_t)blockIdx.x * 8192 + rBase + tid] = s;
    }
}

// ---------------------------------------------------------------------------
// denom[r] = sum of 64 column-block partials
// ---------------------------------------------------------------------------
__global__ void reduce_denom_kernel()
{
    const int r = blockIdx.x * blockDim.x + threadIdx.x;
    float s = 0.0f;
#pragma unroll
    for (int cb = 0; cb < 64; cb++) s += g_partial[(size_t)cb * 8192 + r];
    g_denom[r] = s;
}

// ---------------------------------------------------------------------------
// Pass B (mma.sync bf16x3): out = (P @ V) / denom. grid = (8 col, 64 row).
// ---------------------------------------------------------------------------
__global__ void __launch_bounds__(256, 1) pv_mma(float* __restrict__ out)
{
    extern __shared__ char dynsmem[];

    const int tid = threadIdx.x;
    const int lane = tid & 31, wid = tid >> 5;
    const int wm = wid >> 2, wn = wid & 3;
    const int rBase = blockIdx.y * 128, cBase = blockIdx.x * 128;
    const uint32_t sb = smem_u32(dynsmem);

    float acc[4][4][4] = {};

    const int NC = 256;  // 8192 / 32
    fill_stage(sb, g_Ph, g_Pl, 8192, rBase, g_VhT, g_VlT, 8192, cBase, 0, tid);
    CP_COMMIT();
    for (int c = 0; c < NC; c++) {
        CP_WAIT0();
        __syncthreads();
        if (c + 1 < NC) {
            fill_stage(sb + ((c + 1) & 1) * STAGE_B,
                       g_Ph, g_Pl, 8192, rBase, g_VhT, g_VlT, 8192, cBase,
                       (c + 1) * 32, tid);
            CP_COMMIT();
        }
        compute_chunk(sb + (c & 1) * STAGE_B, wm, wn, lane, acc);
    }

    const int g = lane >> 2, t4 = lane & 3;
#pragma unroll
    for (int ma = 0; ma < 4; ma++) {
        const int m_lo = rBase + wm * 64 + ma * 16 + g;
        const int m_hi = m_lo + 8;
        const float inv_lo = 1.0f / g_denom[m_lo];
        const float inv_hi = 1.0f / g_denom[m_hi];
#pragma unroll
        for (int na = 0; na < 4; na++) {
            const int n = cBase + wn * 32 + na * 8 + t4 * 2;
            float2 v0, v1;
            v0.x = acc[ma][na][0] * inv_lo; v0.y = acc[ma][na][1] * inv_lo;
            v1.x = acc[ma][na][2] * inv_hi; v1.y = acc[ma][na][3] * inv_hi;
            *(float2*)(out + (size_t)m_lo * 1024 + n) = v0;
            *(float2*)(out + (size_t)m_hi * 1024 + n) = v1;
        }
    }
}

// ---------------------------------------------------------------------------
// kernel_launch: graph-capturable, allocation-free
// ---------------------------------------------------------------------------
extern "C" void kernel_launch(void* const* d_in, const int* in_sizes, int n_in,
                              void* d_out, int out_size)
{
    int iMain = -1, iOther = -1, iFix = -1, iMask = -1,
        iWq = -1, iWk = -1, iBq = -1, iBk = -1;
    for (int i = 0; i < n_in; i++) {
        const long s = in_sizes[i];
        if (s == 67108864)      iMask = i;
        else if (s == 8388608)  { if (iMain < 0) iMain = i; else iOther = i; }
        else if (s == 524288)   { if (iWq   < 0) iWq   = i; else iWk    = i; }
        else if (s == 8192)     iFix = i;
        else if (s == 512)      { if (iBq   < 0) iBq   = i; else iBk    = i; }
    }

    const float* main_feat  = (const float*)d_in[iMain];
    const float* other_feat = (const float*)d_in[iOther];
    const float* fix_feat   = (const float*)d_in[iFix];
    const void*  mask_raw   = d_in[iMask];
    const float* Wq         = (const float*)d_in[iWq];
    const float* bq         = (const float*)d_in[iBq];
    const float* Wk         = (const float*)d_in[iWk];
    const float* bk         = (const float*)d_in[iBk];
    float* out              = (float*)d_out;
    (void)out_size;

    static int configured = 0;
    if (!configured) {
        cudaFuncSetAttribute(attn_exp_mma,
                             cudaFuncAttributeMaxDynamicSharedMemorySize, DYN_SMEM);
        cudaFuncSetAttribute(pv_mma,
                             cudaFuncAttributeMaxDynamicSharedMemorySize, DYN_SMEM);
        configured = 1;
    }

    detect_mask_kernel<<<1, 256>>>((const unsigned int*)mask_raw);
    convert_mask_kernel<<<65536, 256>>>(mask_raw);

    proj_kernel<0><<<dim3(4, 64), 256>>>(main_feat, Wq, bq);
    proj_kernel<1><<<dim3(4, 64), 256>>>(other_feat, Wk, bk);

    transpose_v_kernel<<<dim3(256, 32), dim3(32, 8)>>>(other_feat, fix_feat);

    attn_exp_mma<<<dim3(64, 64), 256, DYN_SMEM>>>();

    reduce_denom_kernel<<<32, 256>>>();

    pv_mma<<<dim3(8, 64), 256, DYN_SMEM>>>(out);
}

// round 11
// speedup vs baseline: 1.1649x; 1.1649x over previous
#include <cuda_runtime.h>
#include <cuda_bf16.h>
#include <cuda_fp16.h>
#include <math.h>
#include <stdint.h>
#include <stddef.h>

// Problem shape: N = M = 8192, QDIM = KDIM = 1024, MID = 512
// ---------------------------------------------------------------------------
// Device scratch (no allocation allowed anywhere)
// ---------------------------------------------------------------------------
static __device__ __nv_bfloat16 g_Qh[(size_t)8192 * 512];
static __device__ __nv_bfloat16 g_Ql[(size_t)8192 * 512];
static __device__ __nv_bfloat16 g_Kh[(size_t)8192 * 512];
static __device__ __nv_bfloat16 g_Kl[(size_t)8192 * 512];
static __device__ __half g_VhT[(size_t)1024 * 8192];   // [n][k] fp16 hi
static __device__ __half g_VlT[(size_t)1024 * 8192];   // [n][k] fp16 lo
static __device__ __half g_Pf[(size_t)8192 * 8192];    // 128 MB fp16 P
static __device__ float g_partial[(size_t)64 * 8192];
static __device__ float g_denom[8192];
static __device__ unsigned char g_M[(size_t)8192 * 8192];
static __device__ int g_mask_w1;

// ---------------------------------------------------------------------------
// PTX helpers (plain sm_80-era ISA; valid on .target sm_100)
// ---------------------------------------------------------------------------
__device__ __forceinline__ uint32_t smem_u32(const void* p) {
    uint32_t a;
    asm("{ .reg .u64 t; cvta.to.shared.u64 t, %1; cvt.u32.u64 %0, t; }"
        : "=r"(a) : "l"(p));
    return a;
}
#define LDSM4(r, addr) \
    asm volatile("ldmatrix.sync.aligned.m8n8.x4.shared.b16 {%0,%1,%2,%3}, [%4];" \
                 : "=r"((r)[0]), "=r"((r)[1]), "=r"((r)[2]), "=r"((r)[3]) \
                 : "r"(addr))
#define MMA16816(d, a, b) \
    asm volatile("mma.sync.aligned.m16n8k16.row.col.f32.bf16.bf16.f32 " \
                 "{%0,%1,%2,%3}, {%4,%5,%6,%7}, {%8,%9}, {%0,%1,%2,%3};" \
                 : "+f"((d)[0]), "+f"((d)[1]), "+f"((d)[2]), "+f"((d)[3]) \
                 : "r"((a)[0]), "r"((a)[1]), "r"((a)[2]), "r"((a)[3]), \
                   "r"((b)[0]), "r"((b)[1]))
#define MMA16816H(d, a, b) \
    asm volatile("mma.sync.aligned.m16n8k16.row.col.f32.f16.f16.f32 " \
                 "{%0,%1,%2,%3}, {%4,%5,%6,%7}, {%8,%9}, {%0,%1,%2,%3};" \
                 : "+f"((d)[0]), "+f"((d)[1]), "+f"((d)[2]), "+f"((d)[3]) \
                 : "r"((a)[0]), "r"((a)[1]), "r"((a)[2]), "r"((a)[3]), \
                   "r"((b)[0]), "r"((b)[1]))
#define CP16(saddr, gptr) \
    asm volatile("cp.async.cg.shared.global [%0], [%1], 16;" \
                 :: "r"(saddr), "l"(gptr))
#define CP_COMMIT() asm volatile("cp.async.commit_group;" ::: "memory")
#define CP_WAIT0()  asm volatile("cp.async.wait_group 0;" ::: "memory")

__device__ __forceinline__ unsigned int pack2(__nv_bfloat16 a, __nv_bfloat16 b) {
    const unsigned short ua = *(const unsigned short*)&a;
    const unsigned short ub = *(const unsigned short*)&b;
    return (unsigned int)ua | ((unsigned int)ub << 16);
}
__device__ __forceinline__ unsigned int pack2h(__half a, __half b) {
    const unsigned short ua = *(const unsigned short*)&a;
    const unsigned short ub = *(const unsigned short*)&b;
    return (unsigned int)ua | ((unsigned int)ub << 16);
}

// smem tile geometry: 128 rows x 32 elems (16-bit), padded row stride 80 B
#define ROWB 80
#define TILE_B (128 * ROWB)            // 10240 B
#define OFF_AH 0
#define OFF_AL (1 * TILE_B)
#define OFF_BH (2 * TILE_B)
#define OFF_BL (3 * TILE_B)
#define STAGE_B (4 * TILE_B)           // 40960 B
#define DYN_SMEM (2 * STAGE_B)         // 81920 B

// Pass-B geometry: 3 tiles per stage (P, Vh, Vl)
#define PV_OFF_P  0
#define PV_OFF_VH (1 * TILE_B)
#define PV_OFF_VL (2 * TILE_B)
#define PV_STAGE_B (3 * TILE_B)        // 30720 B
#define DYN_SMEM_PV (2 * PV_STAGE_B)   // 61440 B

// Fill one 4-tile stage via cp.async (proven in R6): 8 x 16B per thread.
__device__ __forceinline__ void fill_stage(
    uint32_t sbase,
    const __nv_bfloat16* __restrict__ Ah, const __nv_bfloat16* __restrict__ Al,
    size_t strideA, int rA,
    const __nv_bfloat16* __restrict__ Bh, const __nv_bfloat16* __restrict__ Bl,
    size_t strideB, int rB,
    int k0, int tid)
{
#pragma unroll
    for (int it = 0; it < 2; it++) {
        const int idx = it * 256 + tid;     // 0..511
        const int row = idx >> 2, seg = idx & 3;
        const uint32_t so = (uint32_t)(row * ROWB + seg * 16);
        const size_t ca = (size_t)(rA + row) * strideA + k0 + seg * 8;
        const size_t cb = (size_t)(rB + row) * strideB + k0 + seg * 8;
        CP16(sbase + OFF_AH + so, Ah + ca);
        CP16(sbase + OFF_AL + so, Al + ca);
        CP16(sbase + OFF_BH + so, Bh + cb);
        CP16(sbase + OFF_BL + so, Bl + cb);
    }
}

// Fill one 3-tile pass-B stage (P, Vh, Vl) — globals only, 6 x 16B per thread.
__device__ __forceinline__ void fill_stage_pv(
    uint32_t sbase, int rBase, int cBase, int k0, int tid)
{
#pragma unroll
    for (int it = 0; it < 2; it++) {
        const int idx = it * 256 + tid;     // 0..511
        const int row = idx >> 2, seg = idx & 3;
        const uint32_t so = (uint32_t)(row * ROWB + seg * 16);
        const size_t cp = (size_t)(rBase + row) * 8192 + k0 + seg * 8;
        const size_t cv = (size_t)(cBase + row) * 8192 + k0 + seg * 8;
        CP16(sbase + PV_OFF_P  + so, g_Pf  + cp);
        CP16(sbase + PV_OFF_VH + so, g_VhT + cv);
        CP16(sbase + PV_OFF_VL + so, g_VlT + cv);
    }
}

// Compute one BK=32 chunk, bf16 3-product (byte-identical to R6-passed).
__device__ __forceinline__ void compute_chunk(
    uint32_t sbase, int wm, int wn, int lane, float acc[4][4][4])
{
    const int a_r = lane & 15, a_c = (lane >> 4) * 8;
    const int b_r = ((lane >> 4) & 1) * 8 + (lane & 7);
    const int b_c = ((lane >> 3) & 1) * 8;
#pragma unroll
    for (int ks = 0; ks < 2; ks++) {
        const int k0 = ks * 16;
        uint32_t ah[4][4], al[4][4];
#pragma unroll
        for (int ma = 0; ma < 4; ma++) {
            const uint32_t ra = sbase + OFF_AH +
                (uint32_t)((wm * 64 + ma * 16 + a_r) * ROWB + (k0 + a_c) * 2);
            LDSM4(ah[ma], ra);
            LDSM4(al[ma], ra + (OFF_AL - OFF_AH));
        }
        uint32_t bh[4][2], bl[4][2];
#pragma unroll
        for (int nb = 0; nb < 2; nb++) {
            const uint32_t rb = sbase + OFF_BH +
                (uint32_t)((wn * 32 + nb * 16 + b_r) * ROWB + (k0 + b_c) * 2);
            uint32_t t[4];
            LDSM4(t, rb);
            bh[nb * 2][0] = t[0]; bh[nb * 2][1] = t[1];
            bh[nb * 2 + 1][0] = t[2]; bh[nb * 2 + 1][1] = t[3];
            LDSM4(t, rb + (OFF_BL - OFF_BH));
            bl[nb * 2][0] = t[0]; bl[nb * 2][1] = t[1];
            bl[nb * 2 + 1][0] = t[2]; bl[nb * 2 + 1][1] = t[3];
        }
#pragma unroll
        for (int ma = 0; ma < 4; ma++)
#pragma unroll
            for (int na = 0; na < 4; na++) {
                MMA16816(acc[ma][na], ah[ma], bh[na]);
                MMA16816(acc[ma][na], ah[ma], bl[na]);
                MMA16816(acc[ma][na], al[ma], bh[na]);
            }
    }
}

// Pass-B chunk: fp16, A single (P), B pair (Vh, Vl) -> 2 products.
__device__ __forceinline__ void compute_chunk_pv(
    uint32_t sbase, int wm, int wn, int lane, float acc[4][4][4])
{
    const int a_r = lane & 15, a_c = (lane >> 4) * 8;
    const int b_r = ((lane >> 4) & 1) * 8 + (lane & 7);
    const int b_c = ((lane >> 3) & 1) * 8;
#pragma unroll
    for (int ks = 0; ks < 2; ks++) {
        const int k0 = ks * 16;
        uint32_t ah[4][4];
#pragma unroll
        for (int ma = 0; ma < 4; ma++) {
            const uint32_t ra = sbase + PV_OFF_P +
                (uint32_t)((wm * 64 + ma * 16 + a_r) * ROWB + (k0 + a_c) * 2);
            LDSM4(ah[ma], ra);
        }
        uint32_t bh[4][2], bl[4][2];
#pragma unroll
        for (int nb = 0; nb < 2; nb++) {
            const uint32_t rb = sbase + PV_OFF_VH +
                (uint32_t)((wn * 32 + nb * 16 + b_r) * ROWB + (k0 + b_c) * 2);
            uint32_t t[4];
            LDSM4(t, rb);
            bh[nb * 2][0] = t[0]; bh[nb * 2][1] = t[1];
            bh[nb * 2 + 1][0] = t[2]; bh[nb * 2 + 1][1] = t[3];
            LDSM4(t, rb + (PV_OFF_VL - PV_OFF_VH));
            bl[nb * 2][0] = t[0]; bl[nb * 2][1] = t[1];
            bl[nb * 2 + 1][0] = t[2]; bl[nb * 2 + 1][1] = t[3];
        }
#pragma unroll
        for (int ma = 0; ma < 4; ma++)
#pragma unroll
            for (int na = 0; na < 4; na++) {
                MMA16816H(acc[ma][na], ah[ma], bh[na]);
                MMA16816H(acc[ma][na], ah[ma], bl[na]);
            }
    }
}

// ---------------------------------------------------------------------------
// Mask dtype detection + normalization (proven)
// ---------------------------------------------------------------------------
__global__ void detect_mask_kernel(const unsigned int* __restrict__ mw) {
    __shared__ int s_gt1, s_f32;
    if (threadIdx.x == 0) { s_gt1 = 0; s_f32 = 0; }
    __syncthreads();
    int gt1 = 0, f32 = 0;
    for (int i = threadIdx.x; i < 65536; i += blockDim.x) {
        const unsigned int w = mw[i];
        if (w == 0x3F800000u) f32 = 1;
        else if (w > 1u) gt1 = 1;
    }
    if (gt1) atomicOr(&s_gt1, 1);
    if (f32) atomicOr(&s_f32, 1);
    __syncthreads();
    if (threadIdx.x == 0) g_mask_w1 = (s_gt1 && !s_f32) ? 1 : 0;
}

__global__ void convert_mask_kernel(const void* __restrict__ mask_raw) {
    const int g = blockIdx.x * blockDim.x + threadIdx.x;
    unsigned int outw;
    if (g_mask_w1) {
        const unsigned int w = ((const unsigned int*)mask_raw)[g];
        outw = ((w & 0x000000FFu) ? 0x00000001u : 0u)
             | ((w & 0x0000FF00u) ? 0x00000100u : 0u)
             | ((w & 0x00FF0000u) ? 0x00010000u : 0u)
             | ((w & 0xFF000000u) ? 0x01000000u : 0u);
    } else {
        const uint4 v = ((const uint4*)mask_raw)[g];
        outw = (v.x ? 0x00000001u : 0u) | (v.y ? 0x00000100u : 0u)
             | (v.z ? 0x00010000u : 0u) | (v.w ? 0x01000000u : 0u);
    }
    ((unsigned int*)g_M)[g] = outw;
}

// ---------------------------------------------------------------------------
// Projection (fp32 SIMT, proven in R6) with split-bf16 epilogue.
// ---------------------------------------------------------------------------
template <int OUTSEL>
__global__ void __launch_bounds__(256) proj_kernel(
    const float* __restrict__ A, const float* __restrict__ W,
    const float* __restrict__ bias)
{
    const int Kd = 1024, Ncols = 512;
    __nv_bfloat16* __restrict__ Ch = (OUTSEL == 0) ? g_Qh : g_Kh;
    __nv_bfloat16* __restrict__ Cl = (OUTSEL == 0) ? g_Ql : g_Kl;

    __shared__ __align__(16) float As[8][128];
    __shared__ __align__(16) float Bs[8][128];

    const int tid = threadIdx.x;
    const int tx = tid & 15, ty = tid >> 4;
    const int row0 = ty * 8, col0 = tx * 8;
    const int rBase = blockIdx.y * 128, cBase = blockIdx.x * 128;
    const int aRow = tid >> 1, aCol = (tid & 1) * 4;
    const int bRow = tid >> 5, bCol = (tid & 31) * 4;

    float acc[8][8] = {};

    for (int k0 = 0; k0 < Kd; k0 += 8) {
        float4 av = *(const float4*)(A + (size_t)(rBase + aRow) * Kd + k0 + aCol);
        As[aCol + 0][aRow] = av.x; As[aCol + 1][aRow] = av.y;
        As[aCol + 2][aRow] = av.z; As[aCol + 3][aRow] = av.w;
        *(float4*)(&Bs[bRow][bCol]) =
            *(const float4*)(W + (size_t)(k0 + bRow) * Ncols + cBase + bCol);
        __syncthreads();
#pragma unroll
        for (int k = 0; k < 8; k++) {
            float a[8], b[8];
#pragma unroll
            for (int i = 0; i < 8; i++) a[i] = As[k][row0 + i];
#pragma unroll
            for (int j = 0; j < 8; j++) b[j] = Bs[k][col0 + j];
#pragma unroll
            for (int i = 0; i < 8; i++)
#pragma unroll
                for (int j = 0; j < 8; j++)
                    acc[i][j] = fmaf(a[i], b[j], acc[i][j]);
        }
        __syncthreads();
    }

#pragma unroll
    for (int i = 0; i < 8; i++) {
        const size_t r = (size_t)(rBase + row0 + i);
#pragma unroll
        for (int j = 0; j < 8; j++) {
            const float x = acc[i][j] + bias[cBase + col0 + j];
            const __nv_bfloat16 h = __float2bfloat16(x);
            const __nv_bfloat16 l = __float2bfloat16(x - __bfloat162float(h));
            Ch[r * Ncols + cBase + col0 + j] = h;
            Cl[r * Ncols + cBase + col0 + j] = l;
        }
    }
}

// ---------------------------------------------------------------------------
// V^T split (fp16): g_VhT/g_VlT[n][k] = split(fix[k] * other[k][n])
// ---------------------------------------------------------------------------
__global__ void transpose_v_kernel(const float* __restrict__ other,
                                   const float* __restrict__ fix)
{
    __shared__ float t[32][33];
    const int kBase = blockIdx.x * 32, nBase = blockIdx.y * 32;
    const int tx = threadIdx.x, ty = threadIdx.y;
#pragma unroll
    for (int j = 0; j < 4; j++) {
        const int k = kBase + ty + j * 8;
        t[ty + j * 8][tx] = fix[k] * other[(size_t)k * 1024 + nBase + tx];
    }
    __syncthreads();
#pragma unroll
    for (int j = 0; j < 4; j++) {
        const int n = nBase + ty + j * 8;
        const float v = t[tx][ty + j * 8];
        const __half h = __float2half(v);
        const __half l = __float2half(v - __half2float(h));
        g_VhT[(size_t)n * 8192 + kBase + tx] = h;
        g_VlT[(size_t)n * 8192 + kBase + tx] = l;
    }
}

// ---------------------------------------------------------------------------
// Pass A (mma bf16x3, mainloop identical to R6): S = Q@K^T / sqrt(512);
// P = mask ? 0 : exp(S) -> fp16 store + per-colblock row sums.
// grid = (64 col, 64 row), 256 thr.
// ---------------------------------------------------------------------------
__global__ void __launch_bounds__(256, 1) attn_exp_mma()
{
    extern __shared__ char dynsmem[];
    __shared__ float red[128][4];

    const int tid = threadIdx.x;
    const int lane = tid & 31, wid = tid >> 5;
    const int wm = wid >> 2, wn = wid & 3;
    const int rBase = blockIdx.y * 128, cBase = blockIdx.x * 128;
    const uint32_t sb = smem_u32(dynsmem);

    float acc[4][4][4] = {};

    const int NC = 16;  // 512 / 32
    fill_stage(sb, g_Qh, g_Ql, 512, rBase, g_Kh, g_Kl, 512, cBase, 0, tid);
    CP_COMMIT();
    for (int c = 0; c < NC; c++) {
        CP_WAIT0();
        __syncthreads();
        if (c + 1 < NC) {
            fill_stage(sb + ((c + 1) & 1) * STAGE_B,
                       g_Qh, g_Ql, 512, rBase, g_Kh, g_Kl, 512, cBase,
                       (c + 1) * 32, tid);
            CP_COMMIT();
        }
        compute_chunk(sb + (c & 1) * STAGE_B, wm, wn, lane, acc);
    }

    // epilogue: exp + mask + fp16 store + rowsums (from the fp16 value so the
    // denominator matches pass B's numerator exactly)
    const float scale = 0.044194173824159216f;  // 1/sqrt(512)
    const int g = lane >> 2, t4 = lane & 3;
    float rs_lo[4] = {}, rs_hi[4] = {};
#pragma unroll
    for (int ma = 0; ma < 4; ma++) {
        const int m_lo = rBase + wm * 64 + ma * 16 + g;
        const int m_hi = m_lo + 8;
#pragma unroll
        for (int na = 0; na < 4; na++) {
            const int n = cBase + wn * 32 + na * 8 + t4 * 2;
            {
                const unsigned short mk =
                    *(const unsigned short*)(g_M + (size_t)m_lo * 8192 + n);
                const float p0 = (mk & 0xFF) ? 0.0f : expf(acc[ma][na][0] * scale);
                const float p1 = (mk >> 8)   ? 0.0f : expf(acc[ma][na][1] * scale);
                const __half h0 = __float2half(p0);
                const __half h1 = __float2half(p1);
                *(unsigned int*)(g_Pf + (size_t)m_lo * 8192 + n) = pack2h(h0, h1);
                rs_lo[ma] += __half2float(h0) + __half2float(h1);
            }
            {
                const unsigned short mk =
                    *(const unsigned short*)(g_M + (size_t)m_hi * 8192 + n);
                const float p0 = (mk & 0xFF) ? 0.0f : expf(acc[ma][na][2] * scale);
                const float p1 = (mk >> 8)   ? 0.0f : expf(acc[ma][na][3] * scale);
                const __half h0 = __float2half(p0);
                const __half h1 = __float2half(p1);
                *(unsigned int*)(g_Pf + (size_t)m_hi * 8192 + n) = pack2h(h0, h1);
                rs_hi[ma] += __half2float(h0) + __half2float(h1);
            }
        }
    }
#pragma unroll
    for (int ma = 0; ma < 4; ma++) {
        float s = rs_lo[ma];
        s += __shfl_xor_sync(0xFFFFFFFFu, s, 1);
        s += __shfl_xor_sync(0xFFFFFFFFu, s, 2);
        float s2 = rs_hi[ma];
        s2 += __shfl_xor_sync(0xFFFFFFFFu, s2, 1);
        s2 += __shfl_xor_sync(0xFFFFFFFFu, s2, 2);
        if (t4 == 0) {
            red[wm * 64 + ma * 16 + g][wn] = s;
            red[wm * 64 + ma * 16 + g + 8][wn] = s2;
        }
    }
    __syncthreads();
    if (tid < 128) {
        const float s = red[tid][0] + red[tid][1] + red[tid][2] + red[tid][3];
        g_partial[(size_t)blockIdx.x * 8192 + rBase + tid] = s;
    }
}

// ---------------------------------------------------------------------------
// denom[r] = sum of 64 column-block partials
// ---------------------------------------------------------------------------
__global__ void reduce_denom_kernel()
{
    const int r = blockIdx.x * blockDim.x + threadIdx.x;
    float s = 0.0f;
#pragma unroll
    for (int cb = 0; cb < 64; cb++) s += g_partial[(size_t)cb * 8192 + r];
    g_denom[r] = s;
}

// ---------------------------------------------------------------------------
// Pass B (fp16, 2 products): out = (P @ V) / denom. grid = (8 col, 64 row).
// ---------------------------------------------------------------------------
__global__ void __launch_bounds__(256, 1) pv_mma(float* __restrict__ out)
{
    extern __shared__ char dynsmem[];

    const int tid = threadIdx.x;
    const int lane = tid & 31, wid = tid >> 5;
    const int wm = wid >> 2, wn = wid & 3;
    const int rBase = blockIdx.y * 128, cBase = blockIdx.x * 128;
    const uint32_t sb = smem_u32(dynsmem);

    float acc[4][4][4] = {};

    const int NC = 256;  // 8192 / 32
    fill_stage_pv(sb, rBase, cBase, 0, tid);
    CP_COMMIT();
    for (int c = 0; c < NC; c++) {
        CP_WAIT0();
        __syncthreads();
        if (c + 1 < NC) {
            fill_stage_pv(sb + ((c + 1) & 1) * PV_STAGE_B,
                          rBase, cBase, (c + 1) * 32, tid);
            CP_COMMIT();
        }
        compute_chunk_pv(sb + (c & 1) * PV_STAGE_B, wm, wn, lane, acc);
    }

    const int g = lane >> 2, t4 = lane & 3;
#pragma unroll
    for (int ma = 0; ma < 4; ma++) {
        const int m_lo = rBase + wm * 64 + ma * 16 + g;
        const int m_hi = m_lo + 8;
        const float inv_lo = 1.0f / g_denom[m_lo];
        const float inv_hi = 1.0f / g_denom[m_hi];
#pragma unroll
        for (int na = 0; na < 4; na++) {
            const int n = cBase + wn * 32 + na * 8 + t4 * 2;
            float2 v0, v1;
            v0.x = acc[ma][na][0] * inv_lo; v0.y = acc[ma][na][1] * inv_lo;
            v1.x = acc[ma][na][2] * inv_hi; v1.y = acc[ma][na][3] * inv_hi;
            *(float2*)(out + (size_t)m_lo * 1024 + n) = v0;
            *(float2*)(out + (size_t)m_hi * 1024 + n) = v1;
        }
    }
}

// ---------------------------------------------------------------------------
// kernel_launch: graph-capturable, allocation-free
// ---------------------------------------------------------------------------
extern "C" void kernel_launch(void* const* d_in, const int* in_sizes, int n_in,
                              void* d_out, int out_size)
{
    int iMain = -1, iOther = -1, iFix = -1, iMask = -1,
        iWq = -1, iWk = -1, iBq = -1, iBk = -1;
    for (int i = 0; i < n_in; i++) {
        const long s = in_sizes[i];
        if (s == 67108864)      iMask = i;
        else if (s == 8388608)  { if (iMain < 0) iMain = i; else iOther = i; }
        else if (s == 524288)   { if (iWq   < 0) iWq   = i; else iWk    = i; }
        else if (s == 8192)     iFix = i;
        else if (s == 512)      { if (iBq   < 0) iBq   = i; else iBk    = i; }
    }

    const float* main_feat  = (const float*)d_in[iMain];
    const float* other_feat = (const float*)d_in[iOther];
    const float* fix_feat   = (const float*)d_in[iFix];
    const void*  mask_raw   = d_in[iMask];
    const float* Wq         = (const float*)d_in[iWq];
    const float* bq         = (const float*)d_in[iBq];
    const float* Wk         = (const float*)d_in[iWk];
    const float* bk         = (const float*)d_in[iBk];
    float* out              = (float*)d_out;
    (void)out_size;

    static int configured = 0;
    if (!configured) {
        cudaFuncSetAttribute(attn_exp_mma,
                             cudaFuncAttributeMaxDynamicSharedMemorySize, DYN_SMEM);
        cudaFuncSetAttribute(pv_mma,
                             cudaFuncAttributeMaxDynamicSharedMemorySize, DYN_SMEM_PV);
        configured = 1;
    }

    detect_mask_kernel<<<1, 256>>>((const unsigned int*)mask_raw);
    convert_mask_kernel<<<65536, 256>>>(mask_raw);

    proj_kernel<0><<<dim3(4, 64), 256>>>(main_feat, Wq, bq);
    proj_kernel<1><<<dim3(4, 64), 256>>>(other_feat, Wk, bk);

    transpose_v_kernel<<<dim3(256, 32), dim3(32, 8)>>>(other_feat, fix_feat);

    attn_exp_mma<<<dim3(64, 64), 256, DYN_SMEM>>>();

    reduce_denom_kernel<<<32, 256>>>();

    pv_mma<<<dim3(8, 64), 256, DYN_SMEM_PV>>>(out);
}

// round 13
// speedup vs baseline: 1.5473x; 1.3283x over previous
#include <cuda_runtime.h>
#include <cuda_fp16.h>
#include <math.h>
#include <stdint.h>
#include <stddef.h>

// Problem shape: N = M = 8192, QDIM = KDIM = 1024, MID = 512
// ---------------------------------------------------------------------------
// Device scratch (no allocation allowed anywhere)
// ---------------------------------------------------------------------------
static __device__ __half g_Qf[(size_t)8192 * 512];     // fp16 Q
static __device__ __half g_Kf[(size_t)8192 * 512];     // fp16 K
static __device__ __half g_Vf[(size_t)1024 * 8192];    // fp16 V^T [n][k]
static __device__ __half g_Pf[(size_t)8192 * 8192];    // 128 MB fp16 P
static __device__ float g_partial[(size_t)64 * 8192];
static __device__ float g_denom[8192];
static __device__ unsigned char g_M[(size_t)8192 * 8192];
static __device__ int g_mask_w1;

// ---------------------------------------------------------------------------
// PTX helpers (plain sm_80-era ISA; valid on .target sm_100)
// ---------------------------------------------------------------------------
__device__ __forceinline__ uint32_t smem_u32(const void* p) {
    uint32_t a;
    asm("{ .reg .u64 t; cvta.to.shared.u64 t, %1; cvt.u32.u64 %0, t; }"
        : "=r"(a) : "l"(p));
    return a;
}
#define LDSM4(r, addr) \
    asm volatile("ldmatrix.sync.aligned.m8n8.x4.shared.b16 {%0,%1,%2,%3}, [%4];" \
                 : "=r"((r)[0]), "=r"((r)[1]), "=r"((r)[2]), "=r"((r)[3]) \
                 : "r"(addr))
#define MMA16816H(d, a, b) \
    asm volatile("mma.sync.aligned.m16n8k16.row.col.f32.f16.f16.f32 " \
                 "{%0,%1,%2,%3}, {%4,%5,%6,%7}, {%8,%9}, {%0,%1,%2,%3};" \
                 : "+f"((d)[0]), "+f"((d)[1]), "+f"((d)[2]), "+f"((d)[3]) \
                 : "r"((a)[0]), "r"((a)[1]), "r"((a)[2]), "r"((a)[3]), \
                   "r"((b)[0]), "r"((b)[1]))
#define CP16(saddr, gptr) \
    asm volatile("cp.async.cg.shared.global [%0], [%1], 16;" \
                 :: "r"(saddr), "l"(gptr))
#define CP_COMMIT() asm volatile("cp.async.commit_group;" ::: "memory")
#define CP_WAIT0()  asm volatile("cp.async.wait_group 0;" ::: "memory")

__device__ __forceinline__ unsigned int pack2h(__half a, __half b) {
    const unsigned short ua = *(const unsigned short*)&a;
    const unsigned short ub = *(const unsigned short*)&b;
    return (unsigned int)ua | ((unsigned int)ub << 16);
}

// smem tile geometry: 128 rows x 32 fp16, padded row stride 80 B (proven)
#define ROWB 80
#define TILE_B (128 * ROWB)            // 10240 B
#define OFF_A 0
#define OFF_B TILE_B
#define STAGE_B (2 * TILE_B)           // 20480 B (2 tiles: A, B)
#define DYN_SMEM (2 * STAGE_B)         // 40960 B (< 48KB default limit)

// Fill one 2-tile stage via cp.async: 4 x 16B per thread.
__device__ __forceinline__ void fill_stage2(
    uint32_t sbase,
    const __half* __restrict__ A, size_t strideA, int rA,
    const __half* __restrict__ B, size_t strideB, int rB,
    int k0, int tid)
{
#pragma unroll
    for (int it = 0; it < 2; it++) {
        const int idx = it * 256 + tid;     // 0..511
        const int row = idx >> 2, seg = idx & 3;
        const uint32_t so = (uint32_t)(row * ROWB + seg * 16);
        CP16(sbase + OFF_A + so, A + (size_t)(rA + row) * strideA + k0 + seg * 8);
        CP16(sbase + OFF_B + so, B + (size_t)(rB + row) * strideB + k0 + seg * 8);
    }
}

// Compute one BK=32 chunk: single fp16 product, 2 k-steps, 4x4 atoms/warp.
__device__ __forceinline__ void compute_chunk1(
    uint32_t sbase, int wm, int wn, int lane, float acc[4][4][4])
{
    const int a_r = lane & 15, a_c = (lane >> 4) * 8;
    const int b_r = ((lane >> 4) & 1) * 8 + (lane & 7);
    const int b_c = ((lane >> 3) & 1) * 8;
#pragma unroll
    for (int ks = 0; ks < 2; ks++) {
        const int k0 = ks * 16;
        uint32_t ah[4][4];
#pragma unroll
        for (int ma = 0; ma < 4; ma++) {
            const uint32_t ra = sbase + OFF_A +
                (uint32_t)((wm * 64 + ma * 16 + a_r) * ROWB + (k0 + a_c) * 2);
            LDSM4(ah[ma], ra);
        }
        uint32_t bh[4][2];
#pragma unroll
        for (int nb = 0; nb < 2; nb++) {
            const uint32_t rb = sbase + OFF_B +
                (uint32_t)((wn * 32 + nb * 16 + b_r) * ROWB + (k0 + b_c) * 2);
            uint32_t t[4];
            LDSM4(t, rb);
            bh[nb * 2][0] = t[0]; bh[nb * 2][1] = t[1];
            bh[nb * 2 + 1][0] = t[2]; bh[nb * 2 + 1][1] = t[3];
        }
#pragma unroll
        for (int ma = 0; ma < 4; ma++)
#pragma unroll
            for (int na = 0; na < 4; na++)
                MMA16816H(acc[ma][na], ah[ma], bh[na]);
    }
}

// ---------------------------------------------------------------------------
// Mask dtype detection + normalization (proven)
// ---------------------------------------------------------------------------
__global__ void detect_mask_kernel(const unsigned int* __restrict__ mw) {
    __shared__ int s_gt1, s_f32;
    if (threadIdx.x == 0) { s_gt1 = 0; s_f32 = 0; }
    __syncthreads();
    int gt1 = 0, f32 = 0;
    for (int i = threadIdx.x; i < 65536; i += blockDim.x) {
        const unsigned int w = mw[i];
        if (w == 0x3F800000u) f32 = 1;
        else if (w > 1u) gt1 = 1;
    }
    if (gt1) atomicOr(&s_gt1, 1);
    if (f32) atomicOr(&s_f32, 1);
    __syncthreads();
    if (threadIdx.x == 0) g_mask_w1 = (s_gt1 && !s_f32) ? 1 : 0;
}

__global__ void convert_mask_kernel(const void* __restrict__ mask_raw) {
    const int g = blockIdx.x * blockDim.x + threadIdx.x;
    unsigned int outw;
    if (g_mask_w1) {
        const unsigned int w = ((const unsigned int*)mask_raw)[g];
        outw = ((w & 0x000000FFu) ? 0x00000001u : 0u)
             | ((w & 0x0000FF00u) ? 0x00000100u : 0u)
             | ((w & 0x00FF0000u) ? 0x00010000u : 0u)
             | ((w & 0xFF000000u) ? 0x01000000u : 0u);
    } else {
        const uint4 v = ((const uint4*)mask_raw)[g];
        outw = (v.x ? 0x00000001u : 0u) | (v.y ? 0x00000100u : 0u)
             | (v.z ? 0x00010000u : 0u) | (v.w ? 0x01000000u : 0u);
    }
    ((unsigned int*)g_M)[g] = outw;
}

// ---------------------------------------------------------------------------
// Projection (fp32 SIMT, proven) with fp16 epilogue.
// ---------------------------------------------------------------------------
template <int OUTSEL>
__global__ void __launch_bounds__(256) proj_kernel(
    const float* __restrict__ A, const float* __restrict__ W,
    const float* __restrict__ bias)
{
    const int Kd = 1024, Ncols = 512;
    __half* __restrict__ C = (OUTSEL == 0) ? g_Qf : g_Kf;

    __shared__ __align__(16) float As[8][128];
    __shared__ __align__(16) float Bs[8][128];

    const int tid = threadIdx.x;
    const int tx = tid & 15, ty = tid >> 4;
    const int row0 = ty * 8, col0 = tx * 8;
    const int rBase = blockIdx.y * 128, cBase = blockIdx.x * 128;
    const int aRow = tid >> 1, aCol = (tid & 1) * 4;
    const int bRow = tid >> 5, bCol = (tid & 31) * 4;

    float acc[8][8] = {};

    for (int k0 = 0; k0 < Kd; k0 += 8) {
        float4 av = *(const float4*)(A + (size_t)(rBase + aRow) * Kd + k0 + aCol);
        As[aCol + 0][aRow] = av.x; As[aCol + 1][aRow] = av.y;
        As[aCol + 2][aRow] = av.z; As[aCol + 3][aRow] = av.w;
        *(float4*)(&Bs[bRow][bCol]) =
            *(const float4*)(W + (size_t)(k0 + bRow) * Ncols + cBase + bCol);
        __syncthreads();
#pragma unroll
        for (int k = 0; k < 8; k++) {
            float a[8], b[8];
#pragma unroll
            for (int i = 0; i < 8; i++) a[i] = As[k][row0 + i];
#pragma unroll
            for (int j = 0; j < 8; j++) b[j] = Bs[k][col0 + j];
#pragma unroll
            for (int i = 0; i < 8; i++)
#pragma unroll
                for (int j = 0; j < 8; j++)
                    acc[i][j] = fmaf(a[i], b[j], acc[i][j]);
        }
        __syncthreads();
    }

#pragma unroll
    for (int i = 0; i < 8; i++) {
        const size_t r = (size_t)(rBase + row0 + i);
#pragma unroll
        for (int j = 0; j < 8; j++) {
            const float x = acc[i][j] + bias[cBase + col0 + j];
            C[r * Ncols + cBase + col0 + j] = __float2half(x);
        }
    }
}

// ---------------------------------------------------------------------------
// V^T fp16: g_Vf[n][k] = fp16(fix[k] * other[k][n])
// ---------------------------------------------------------------------------
__global__ void transpose_v_kernel(const float* __restrict__ other,
                                   const float* __restrict__ fix)
{
    __shared__ float t[32][33];
    const int kBase = blockIdx.x * 32, nBase = blockIdx.y * 32;
    const int tx = threadIdx.x, ty = threadIdx.y;
#pragma unroll
    for (int j = 0; j < 4; j++) {
        const int k = kBase + ty + j * 8;
        t[ty + j * 8][tx] = fix[k] * other[(size_t)k * 1024 + nBase + tx];
    }
    __syncthreads();
#pragma unroll
    for (int j = 0; j < 4; j++) {
        const int n = nBase + ty + j * 8;
        g_Vf[(size_t)n * 8192 + kBase + tx] = __float2half(t[tx][ty + j * 8]);
    }
}

// ---------------------------------------------------------------------------
// Pass A (fp16 1-product): S = Q@K^T / sqrt(512); P = mask ? 0 : exp(S)
// -> fp16 store + per-colblock row sums. grid = (64 col, 64 row), 256 thr.
// ---------------------------------------------------------------------------
__global__ void __launch_bounds__(256, 1) attn_exp_mma()
{
    extern __shared__ char dynsmem[];
    __shared__ float red[128][4];

    const int tid = threadIdx.x;
    const int lane = tid & 31, wid = tid >> 5;
    const int wm = wid >> 2, wn = wid & 3;
    const int rBase = blockIdx.y * 128, cBase = blockIdx.x * 128;
    const uint32_t sb = smem_u32(dynsmem);

    float acc[4][4][4] = {};

    const int NC = 16;  // 512 / 32
    fill_stage2(sb, g_Qf, 512, rBase, g_Kf, 512, cBase, 0, tid);
    CP_COMMIT();
    for (int c = 0; c < NC; c++) {
        CP_WAIT0();
        __syncthreads();
        if (c + 1 < NC) {
            fill_stage2(sb + ((c + 1) & 1) * STAGE_B,
                        g_Qf, 512, rBase, g_Kf, 512, cBase, (c + 1) * 32, tid);
            CP_COMMIT();
        }
        compute_chunk1(sb + (c & 1) * STAGE_B, wm, wn, lane, acc);
    }

    // epilogue: exp + mask + fp16 store + rowsums (from the fp16 value so the
    // denominator matches pass B's numerator exactly)
    const float scale = 0.044194173824159216f;  // 1/sqrt(512)
    const int g = lane >> 2, t4 = lane & 3;
    float rs_lo[4] = {}, rs_hi[4] = {};
#pragma unroll
    for (int ma = 0; ma < 4; ma++) {
        const int m_lo = rBase + wm * 64 + ma * 16 + g;
        const int m_hi = m_lo + 8;
#pragma unroll
        for (int na = 0; na < 4; na++) {
            const int n = cBase + wn * 32 + na * 8 + t4 * 2;
            {
                const unsigned short mk =
                    *(const unsigned short*)(g_M + (size_t)m_lo * 8192 + n);
                const float p0 = (mk & 0xFF) ? 0.0f : expf(acc[ma][na][0] * scale);
                const float p1 = (mk >> 8)   ? 0.0f : expf(acc[ma][na][1] * scale);
                const __half h0 = __float2half(p0);
                const __half h1 = __float2half(p1);
                *(unsigned int*)(g_Pf + (size_t)m_lo * 8192 + n) = pack2h(h0, h1);
                rs_lo[ma] += __half2float(h0) + __half2float(h1);
            }
            {
                const unsigned short mk =
                    *(const unsigned short*)(g_M + (size_t)m_hi * 8192 + n);
                const float p0 = (mk & 0xFF) ? 0.0f : expf(acc[ma][na][2] * scale);
                const float p1 = (mk >> 8)   ? 0.0f : expf(acc[ma][na][3] * scale);
                const __half h0 = __float2half(p0);
                const __half h1 = __float2half(p1);
                *(unsigned int*)(g_Pf + (size_t)m_hi * 8192 + n) = pack2h(h0, h1);
                rs_hi[ma] += __half2float(h0) + __half2float(h1);
            }
        }
    }
#pragma unroll
    for (int ma = 0; ma < 4; ma++) {
        float s = rs_lo[ma];
        s += __shfl_xor_sync(0xFFFFFFFFu, s, 1);
        s += __shfl_xor_sync(0xFFFFFFFFu, s, 2);
        float s2 = rs_hi[ma];
        s2 += __shfl_xor_sync(0xFFFFFFFFu, s2, 1);
        s2 += __shfl_xor_sync(0xFFFFFFFFu, s2, 2);
        if (t4 == 0) {
            red[wm * 64 + ma * 16 + g][wn] = s;
            red[wm * 64 + ma * 16 + g + 8][wn] = s2;
        }
    }
    __syncthreads();
    if (tid < 128) {
        const float s = red[tid][0] + red[tid][1] + red[tid][2] + red[tid][3];
        g_partial[(size_t)blockIdx.x * 8192 + rBase + tid] = s;
    }
}

// ---------------------------------------------------------------------------
// denom[r] = sum of 64 column-block partials
// ---------------------------------------------------------------------------
__global__ void reduce_denom_kernel()
{
    const int r = blockIdx.x * blockDim.x + threadIdx.x;
    float s = 0.0f;
#pragma unroll
    for (int cb = 0; cb < 64; cb++) s += g_partial[(size_t)cb * 8192 + r];
    g_denom[r] = s;
}

// ---------------------------------------------------------------------------
// Pass B (fp16 1-product): out = (P @ V) / denom. grid = (8 col, 64 row).
// ---------------------------------------------------------------------------
__global__ void __launch_bounds__(256, 1) pv_mma(float* __restrict__ out)
{
    extern __shared__ char dynsmem[];

    const int tid = threadIdx.x;
    const int lane = tid & 31, wid = tid >> 5;
    const int wm = wid >> 2, wn = wid & 3;
    const int rBase = blockIdx.y * 128, cBase = blockIdx.x * 128;
    const uint32_t sb = smem_u32(dynsmem);

    float acc[4][4][4] = {};

    const int NC = 256;  // 8192 / 32
    fill_stage2(sb, g_Pf, 8192, rBase, g_Vf, 8192, cBase, 0, tid);
    CP_COMMIT();
    for (int c = 0; c < NC; c++) {
        CP_WAIT0();
        __syncthreads();
        if (c + 1 < NC) {
            fill_stage2(sb + ((c + 1) & 1) * STAGE_B,
                        g_Pf, 8192, rBase, g_Vf, 8192, cBase, (c + 1) * 32, tid);
            CP_COMMIT();
        }
        compute_chunk1(sb + (c & 1) * STAGE_B, wm, wn, lane, acc);
    }

    const int g = lane >> 2, t4 = lane & 3;
#pragma unroll
    for (int ma = 0; ma < 4; ma++) {
        const int m_lo = rBase + wm * 64 + ma * 16 + g;
        const int m_hi = m_lo + 8;
        const float inv_lo = 1.0f / g_denom[m_lo];
        const float inv_hi = 1.0f / g_denom[m_hi];
#pragma unroll
        for (int na = 0; na < 4; na++) {
            const int n = cBase + wn * 32 + na * 8 + t4 * 2;
            float2 v0, v1;
            v0.x = acc[ma][na][0] * inv_lo; v0.y = acc[ma][na][1] * inv_lo;
            v1.x = acc[ma][na][2] * inv_hi; v1.y = acc[ma][na][3] * inv_hi;
            *(float2*)(out + (size_t)m_lo * 1024 + n) = v0;
            *(float2*)(out + (size_t)m_hi * 1024 + n) = v1;
        }
    }
}

// ---------------------------------------------------------------------------
// kernel_launch: graph-capturable, allocation-free
// ---------------------------------------------------------------------------
extern "C" void kernel_launch(void* const* d_in, const int* in_sizes, int n_in,
                              void* d_out, int out_size)
{
    int iMain = -1, iOther = -1, iFix = -1, iMask = -1,
        iWq = -1, iWk = -1, iBq = -1, iBk = -1;
    for (int i = 0; i < n_in; i++) {
        const long s = in_sizes[i];
        if (s == 67108864)      iMask = i;
        else if (s == 8388608)  { if (iMain < 0) iMain = i; else iOther = i; }
        else if (s == 524288)   { if (iWq   < 0) iWq   = i; else iWk    = i; }
        else if (s == 8192)     iFix = i;
        else if (s == 512)      { if (iBq   < 0) iBq   = i; else iBk    = i; }
    }

    const float* main_feat  = (const float*)d_in[iMain];
    const float* other_feat = (const float*)d_in[iOther];
    const float* fix_feat   = (const float*)d_in[iFix];
    const void*  mask_raw   = d_in[iMask];
    const float* Wq         = (const float*)d_in[iWq];
    const float* bq         = (const float*)d_in[iBq];
    const float* Wk         = (const float*)d_in[iWk];
    const float* bk         = (const float*)d_in[iBk];
    float* out              = (float*)d_out;
    (void)out_size;

    detect_mask_kernel<<<1, 256>>>((const unsigned int*)mask_raw);
    convert_mask_kernel<<<65536, 256>>>(mask_raw);

    proj_kernel<0><<<dim3(4, 64), 256>>>(main_feat, Wq, bq);
    proj_kernel<1><<<dim3(4, 64), 256>>>(other_feat, Wk, bk);

    transpose_v_kernel<<<dim3(256, 32), dim3(32, 8)>>>(other_feat, fix_feat);

    attn_exp_mma<<<dim3(64, 64), 256, DYN_SMEM>>>();

    reduce_denom_kernel<<<32, 256>>>();

    pv_mma<<<dim3(8, 64), 256, DYN_SMEM>>>(out);
}

// round 16
// speedup vs baseline: 1.7174x; 1.1099x over previous
#include <cuda_runtime.h>
#include <cuda_fp16.h>
#include <math.h>
#include <stdint.h>
#include <stddef.h>

// Problem shape: N = M = 8192, QDIM = KDIM = 1024, MID = 512
// ---------------------------------------------------------------------------
// Device scratch (no allocation allowed anywhere)
// ---------------------------------------------------------------------------
static __device__ __half g_Qf[(size_t)8192 * 512];     // fp16 Q
static __device__ __half g_Kf[(size_t)8192 * 512];     // fp16 K
static __device__ __half g_Vf[(size_t)1024 * 8192];    // fp16 V^T [n][k]
static __device__ __half g_Pf[(size_t)8192 * 8192];    // 128 MB fp16 P
static __device__ float g_partial[(size_t)64 * 8192];
static __device__ float g_denom[8192];
static __device__ int g_mask_w1;

// ---------------------------------------------------------------------------
// PTX helpers (plain sm_80-era ISA; valid on .target sm_100)
// ---------------------------------------------------------------------------
__device__ __forceinline__ uint32_t smem_u32(const void* p) {
    uint32_t a;
    asm("{ .reg .u64 t; cvta.to.shared.u64 t, %1; cvt.u32.u64 %0, t; }"
        : "=r"(a) : "l"(p));
    return a;
}
#define LDSM4(r, addr) \
    asm volatile("ldmatrix.sync.aligned.m8n8.x4.shared.b16 {%0,%1,%2,%3}, [%4];" \
                 : "=r"((r)[0]), "=r"((r)[1]), "=r"((r)[2]), "=r"((r)[3]) \
                 : "r"(addr))
#define MMA16816H(d, a, b) \
    asm volatile("mma.sync.aligned.m16n8k16.row.col.f32.f16.f16.f32 " \
                 "{%0,%1,%2,%3}, {%4,%5,%6,%7}, {%8,%9}, {%0,%1,%2,%3};" \
                 : "+f"((d)[0]), "+f"((d)[1]), "+f"((d)[2]), "+f"((d)[3]) \
                 : "r"((a)[0]), "r"((a)[1]), "r"((a)[2]), "r"((a)[3]), \
                   "r"((b)[0]), "r"((b)[1]))
#define CP16(saddr, gptr) \
    asm volatile("cp.async.cg.shared.global [%0], [%1], 16;" \
                 :: "r"(saddr), "l"(gptr))
#define CP_COMMIT() asm volatile("cp.async.commit_group;" ::: "memory")
#define CP_WAIT0()  asm volatile("cp.async.wait_group 0;" ::: "memory")

__device__ __forceinline__ unsigned int pack2h(__half a, __half b) {
    const unsigned short ua = *(const unsigned short*)&a;
    const unsigned short ub = *(const unsigned short*)&b;
    return (unsigned int)ua | ((unsigned int)ub << 16);
}

// smem tile geometry: 128 rows x 32 fp16, padded row stride 80 B (proven)
#define ROWB 80
#define TILE_B (128 * ROWB)            // 10240 B
#define OFF_A 0
#define OFF_B TILE_B
#define STAGE_B (2 * TILE_B)           // 20480 B (2 tiles: A, B)
#define DYN_SMEM (2 * STAGE_B)         // 40960 B (< 48KB default limit)

// Fill one 2-tile stage via cp.async: 4 x 16B per thread.
__device__ __forceinline__ void fill_stage2(
    uint32_t sbase,
    const __half* __restrict__ A, size_t strideA, int rA,
    const __half* __restrict__ B, size_t strideB, int rB,
    int k0, int tid)
{
#pragma unroll
    for (int it = 0; it < 2; it++) {
        const int idx = it * 256 + tid;     // 0..511
        const int row = idx >> 2, seg = idx & 3;
        const uint32_t so = (uint32_t)(row * ROWB + seg * 16);
        CP16(sbase + OFF_A + so, A + (size_t)(rA + row) * strideA + k0 + seg * 8);
        CP16(sbase + OFF_B + so, B + (size_t)(rB + row) * strideB + k0 + seg * 8);
    }
}

// Compute one BK=32 chunk: single fp16 product, 2 k-steps, 4x4 atoms/warp.
__device__ __forceinline__ void compute_chunk1(
    uint32_t sbase, int wm, int wn, int lane, float acc[4][4][4])
{
    const int a_r = lane & 15, a_c = (lane >> 4) * 8;
    const int b_r = ((lane >> 4) & 1) * 8 + (lane & 7);
    const int b_c = ((lane >> 3) & 1) * 8;
#pragma unroll
    for (int ks = 0; ks < 2; ks++) {
        const int k0 = ks * 16;
        uint32_t ah[4][4];
#pragma unroll
        for (int ma = 0; ma < 4; ma++) {
            const uint32_t ra = sbase + OFF_A +
                (uint32_t)((wm * 64 + ma * 16 + a_r) * ROWB + (k0 + a_c) * 2);
            LDSM4(ah[ma], ra);
        }
        uint32_t bh[4][2];
#pragma unroll
        for (int nb = 0; nb < 2; nb++) {
            const uint32_t rb = sbase + OFF_B +
                (uint32_t)((wn * 32 + nb * 16 + b_r) * ROWB + (k0 + b_c) * 2);
            uint32_t t[4];
            LDSM4(t, rb);
            bh[nb * 2][0] = t[0]; bh[nb * 2][1] = t[1];
            bh[nb * 2 + 1][0] = t[2]; bh[nb * 2 + 1][1] = t[3];
        }
#pragma unroll
        for (int ma = 0; ma < 4; ma++)
#pragma unroll
            for (int na = 0; na < 4; na++)
                MMA16816H(acc[ma][na], ah[ma], bh[na]);
    }
}

// ---------------------------------------------------------------------------
// Mask dtype detection (proven). Pass A reads the raw mask directly.
// ---------------------------------------------------------------------------
__global__ void detect_mask_kernel(const unsigned int* __restrict__ mw) {
    __shared__ int s_gt1, s_f32;
    if (threadIdx.x == 0) { s_gt1 = 0; s_f32 = 0; }
    __syncthreads();
    int gt1 = 0, f32 = 0;
    for (int i = threadIdx.x; i < 65536; i += blockDim.x) {
        const unsigned int w = mw[i];
        if (w == 0x3F800000u) f32 = 1;
        else if (w > 1u) gt1 = 1;
    }
    if (gt1) atomicOr(&s_gt1, 1);
    if (f32) atomicOr(&s_f32, 1);
    __syncthreads();
    if (threadIdx.x == 0) g_mask_w1 = (s_gt1 && !s_f32) ? 1 : 0;
}

// ---------------------------------------------------------------------------
// Projection (fp32 SIMT, proven body) — both Q and K in ONE launch.
// blockIdx.z selects (A, W, bias, C): z=0 -> Q from main/Wq, z=1 -> K.
// grid = (4, 64, 2), 256 thr.
// ---------------------------------------------------------------------------
__global__ void __launch_bounds__(256) proj_kernel(
    const float* __restrict__ A0, const float* __restrict__ A1,
    const float* __restrict__ W0, const float* __restrict__ W1,
    const float* __restrict__ b0, const float* __restrict__ b1)
{
    const int Kd = 1024, Ncols = 512;
    const int sel = blockIdx.z;
    const float* __restrict__ A    = sel ? A1 : A0;
    const float* __restrict__ W    = sel ? W1 : W0;
    const float* __restrict__ bias = sel ? b1 : b0;
    __half* __restrict__ C         = sel ? g_Kf : g_Qf;

    __shared__ __align__(16) float As[8][128];
    __shared__ __align__(16) float Bs[8][128];

    const int tid = threadIdx.x;
    const int tx = tid & 15, ty = tid >> 4;
    const int row0 = ty * 8, col0 = tx * 8;
    const int rBase = blockIdx.y * 128, cBase = blockIdx.x * 128;
    const int aRow = tid >> 1, aCol = (tid & 1) * 4;
    const int bRow = tid >> 5, bCol = (tid & 31) * 4;

    float acc[8][8] = {};

    for (int k0 = 0; k0 < Kd; k0 += 8) {
        float4 av = *(const float4*)(A + (size_t)(rBase + aRow) * Kd + k0 + aCol);
        As[aCol + 0][aRow] = av.x; As[aCol + 1][aRow] = av.y;
        As[aCol + 2][aRow] = av.z; As[aCol + 3][aRow] = av.w;
        *(float4*)(&Bs[bRow][bCol]) =
            *(const float4*)(W + (size_t)(k0 + bRow) * Ncols + cBase + bCol);
        __syncthreads();
#pragma unroll
        for (int k = 0; k < 8; k++) {
            float a[8], b[8];
#pragma unroll
            for (int i = 0; i < 8; i++) a[i] = As[k][row0 + i];
#pragma unroll
            for (int j = 0; j < 8; j++) b[j] = Bs[k][col0 + j];
#pragma unroll
            for (int i = 0; i < 8; i++)
#pragma unroll
                for (int j = 0; j < 8; j++)
                    acc[i][j] = fmaf(a[i], b[j], acc[i][j]);
        }
        __syncthreads();
    }

#pragma unroll
    for (int i = 0; i < 8; i++) {
        const size_t r = (size_t)(rBase + row0 + i);
#pragma unroll
        for (int j = 0; j < 8; j++) {
            const float x = acc[i][j] + bias[cBase + col0 + j];
            C[r * Ncols + cBase + col0 + j] = __float2half(x);
        }
    }
}

// ---------------------------------------------------------------------------
// V^T fp16: g_Vf[n][k] = fp16(fix[k] * other[k][n])
// ---------------------------------------------------------------------------
__global__ void transpose_v_kernel(const float* __restrict__ other,
                                   const float* __restrict__ fix)
{
    __shared__ float t[32][33];
    const int kBase = blockIdx.x * 32, nBase = blockIdx.y * 32;
    const int tx = threadIdx.x, ty = threadIdx.y;
#pragma unroll
    for (int j = 0; j < 4; j++) {
        const int k = kBase + ty + j * 8;
        t[ty + j * 8][tx] = fix[k] * other[(size_t)k * 1024 + nBase + tx];
    }
    __syncthreads();
#pragma unroll
    for (int j = 0; j < 4; j++) {
        const int n = nBase + ty + j * 8;
        g_Vf[(size_t)n * 8192 + kBase + tx] = __float2half(t[tx][ty + j * 8]);
    }
}

// ---------------------------------------------------------------------------
// Read 2 mask flags (cols n, n+1 of row m) from the raw mask, dtype-branched.
// Returns bit0 = col n masked, bit8 = col n+1 masked.
// ---------------------------------------------------------------------------
__device__ __forceinline__ unsigned int mask2(const void* __restrict__ mraw,
                                              int w1, size_t m, int n)
{
    if (w1) {
        return *(const unsigned short*)((const unsigned char*)mraw + m * 8192 + n);
    } else {
        const uint2 v = *(const uint2*)((const unsigned int*)mraw + m * 8192 + n);
        return (v.x ? 1u : 0u) | (v.y ? 0x100u : 0u);
    }
}

// ---------------------------------------------------------------------------
// Pass A (fp16 1-product): S = Q@K^T / sqrt(512); P = mask ? 0 : exp(S)
// -> fp16 store + per-colblock row sums. grid = (64 col, 64 row), 256 thr.
// ---------------------------------------------------------------------------
__global__ void __launch_bounds__(256, 1) attn_exp_mma(const void* __restrict__ mraw)
{
    extern __shared__ char dynsmem[];
    __shared__ float red[128][4];

    const int tid = threadIdx.x;
    const int lane = tid & 31, wid = tid >> 5;
    const int wm = wid >> 2, wn = wid & 3;
    const int rBase = blockIdx.y * 128, cBase = blockIdx.x * 128;
    const uint32_t sb = smem_u32(dynsmem);
    const int w1 = g_mask_w1;

    float acc[4][4][4] = {};

    const int NC = 16;  // 512 / 32
    fill_stage2(sb, g_Qf, 512, rBase, g_Kf, 512, cBase, 0, tid);
    CP_COMMIT();
    for (int c = 0; c < NC; c++) {
        CP_WAIT0();
        __syncthreads();
        if (c + 1 < NC) {
            fill_stage2(sb + ((c + 1) & 1) * STAGE_B,
                        g_Qf, 512, rBase, g_Kf, 512, cBase, (c + 1) * 32, tid);
            CP_COMMIT();
        }
        compute_chunk1(sb + (c & 1) * STAGE_B, wm, wn, lane, acc);
    }

    // epilogue: exp + mask + fp16 store + rowsums (from the fp16 value so the
    // denominator matches pass B's numerator exactly)
    const float scale = 0.044194173824159216f;  // 1/sqrt(512)
    const int g = lane >> 2, t4 = lane & 3;
    float rs_lo[4] = {}, rs_hi[4] = {};
#pragma unroll
    for (int ma = 0; ma < 4; ma++) {
        const int m_lo = rBase + wm * 64 + ma * 16 + g;
        const int m_hi = m_lo + 8;
#pragma unroll
        for (int na = 0; na < 4; na++) {
            const int n = cBase + wn * 32 + na * 8 + t4 * 2;
            {
                const unsigned int mk = mask2(mraw, w1, (size_t)m_lo, n);
                const float p0 = (mk & 0xFF) ? 0.0f : expf(acc[ma][na][0] * scale);
                const float p1 = (mk >> 8)   ? 0.0f : expf(acc[ma][na][1] * scale);
                const __half h0 = __float2half(p0);
                const __half h1 = __float2half(p1);
                *(unsigned int*)(g_Pf + (size_t)m_lo * 8192 + n) = pack2h(h0, h1);
                rs_lo[ma] += __half2float(h0) + __half2float(h1);
            }
            {
                const unsigned int mk = mask2(mraw, w1, (size_t)m_hi, n);
                const float p0 = (mk & 0xFF) ? 0.0f : expf(acc[ma][na][2] * scale);
                const float p1 = (mk >> 8)   ? 0.0f : expf(acc[ma][na][3] * scale);
                const __half h0 = __float2half(p0);
                const __half h1 = __float2half(p1);
                *(unsigned int*)(g_Pf + (size_t)m_hi * 8192 + n) = pack2h(h0, h1);
                rs_hi[ma] += __half2float(h0) + __half2float(h1);
            }
        }
    }
#pragma unroll
    for (int ma = 0; ma < 4; ma++) {
        float s = rs_lo[ma];
        s += __shfl_xor_sync(0xFFFFFFFFu, s, 1);
        s += __shfl_xor_sync(0xFFFFFFFFu, s, 2);
        float s2 = rs_hi[ma];
        s2 += __shfl_xor_sync(0xFFFFFFFFu, s2, 1);
        s2 += __shfl_xor_sync(0xFFFFFFFFu, s2, 2);
        if (t4 == 0) {
            red[wm * 64 + ma * 16 + g][wn] = s;
            red[wm * 64 + ma * 16 + g + 8][wn] = s2;
        }
    }
    __syncthreads();
    if (tid < 128) {
        const float s = red[tid][0] + red[tid][1] + red[tid][2] + red[tid][3];
        g_partial[(size_t)blockIdx.x * 8192 + rBase + tid] = s;
    }
}

// ---------------------------------------------------------------------------
// denom[r] = sum of 64 column-block partials
// ---------------------------------------------------------------------------
__global__ void reduce_denom_kernel()
{
    const int r = blockIdx.x * blockDim.x + threadIdx.x;
    float s = 0.0f;
#pragma unroll
    for (int cb = 0; cb < 64; cb++) s += g_partial[(size_t)cb * 8192 + r];
    g_denom[r] = s;
}

// ---------------------------------------------------------------------------
// Pass B (fp16 1-product): out = (P @ V) / denom. grid = (8 col, 64 row).
// ---------------------------------------------------------------------------
__global__ void __launch_bounds__(256, 1) pv_mma(float* __restrict__ out)
{
    extern __shared__ char dynsmem[];

    const int tid = threadIdx.x;
    const int lane = tid & 31, wid = tid >> 5;
    const int wm = wid >> 2, wn = wid & 3;
    const int rBase = blockIdx.y * 128, cBase = blockIdx.x * 128;
    const uint32_t sb = smem_u32(dynsmem);

    float acc[4][4][4] = {};

    const int NC = 256;  // 8192 / 32
    fill_stage2(sb, g_Pf, 8192, rBase, g_Vf, 8192, cBase, 0, tid);
    CP_COMMIT();
    for (int c = 0; c < NC; c++) {
        CP_WAIT0();
        __syncthreads();
        if (c + 1 < NC) {
            fill_stage2(sb + ((c + 1) & 1) * STAGE_B,
                        g_Pf, 8192, rBase, g_Vf, 8192, cBase, (c + 1) * 32, tid);
            CP_COMMIT();
        }
        compute_chunk1(sb + (c & 1) * STAGE_B, wm, wn, lane, acc);
    }

    const int g = lane >> 2, t4 = lane & 3;
#pragma unroll
    for (int ma = 0; ma < 4; ma++) {
        const int m_lo = rBase + wm * 64 + ma * 16 + g;
        const int m_hi = m_lo + 8;
        const float inv_lo = 1.0f / g_denom[m_lo];
        const float inv_hi = 1.0f / g_denom[m_hi];
#pragma unroll
        for (int na = 0; na < 4; na++) {
            const int n = cBase + wn * 32 + na * 8 + t4 * 2;
            float2 v0, v1;
            v0.x = acc[ma][na][0] * inv_lo; v0.y = acc[ma][na][1] * inv_lo;
            v1.x = acc[ma][na][2] * inv_hi; v1.y = acc[ma][na][3] * inv_hi;
            *(float2*)(out + (size_t)m_lo * 1024 + n) = v0;
            *(float2*)(out + (size_t)m_hi * 1024 + n) = v1;
        }
    }
}

// ---------------------------------------------------------------------------
// kernel_launch: graph-capturable, allocation-free
// ---------------------------------------------------------------------------
extern "C" void kernel_launch(void* const* d_in, const int* in_sizes, int n_in,
                              void* d_out, int out_size)
{
    int iMain = -1, iOther = -1, iFix = -1, iMask = -1,
        iWq = -1, iWk = -1, iBq = -1, iBk = -1;
    for (int i = 0; i < n_in; i++) {
        const long s = in_sizes[i];
        if (s == 67108864)      iMask = i;
        else if (s == 8388608)  { if (iMain < 0) iMain = i; else iOther = i; }
        else if (s == 524288)   { if (iWq   < 0) iWq   = i; else iWk    = i; }
        else if (s == 8192)     iFix = i;
        else if (s == 512)      { if (iBq   < 0) iBq   = i; else iBk    = i; }
    }

    const float* main_feat  = (const float*)d_in[iMain];
    const float* other_feat = (const float*)d_in[iOther];
    const float* fix_feat   = (const float*)d_in[iFix];
    const void*  mask_raw   = d_in[iMask];
    const float* Wq         = (const float*)d_in[iWq];
    const float* bq         = (const float*)d_in[iBq];
    const float* Wk         = (const float*)d_in[iWk];
    const float* bk         = (const float*)d_in[iBk];
    float* out              = (float*)d_out;
    (void)out_size;

    detect_mask_kernel<<<1, 256>>>((const unsigned int*)mask_raw);

    // Q and K projections fused into one launch (blockIdx.z selects)
    proj_kernel<<<dim3(4, 64, 2), 256>>>(main_feat, other_feat, Wq, Wk, bq, bk);

    transpose_v_kernel<<<dim3(256, 32), dim3(32, 8)>>>(other_feat, fix_feat);

    attn_exp_mma<<<dim3(64, 64), 256, DYN_SMEM>>>(mask_raw);

    reduce_denom_kernel<<<32, 256>>>();

    pv_mma<<<dim3(8, 64), 256, DYN_SMEM>>>(out);
}